// round 9
// baseline (speedup 1.0000x reference)
#include <cuda_runtime.h>
#include <math.h>
#include <stdint.h>

#define B_N 4096
#define D_N 16384

// W_FIRST = 2 - 10 * (2/49), W_LAST = 2 - W_FIRST, batch_step = (W_FIRST-W_LAST)/(B-1)
#define EPOCH_STEP (2.0 / 49.0)
#define W_FIRST_D  (2.0 - 10.0 * EPOCH_STEP)   /* ~1.5918367346938775 */
#define W_LAST_D   (2.0 - W_FIRST_D)
#define BATCH_STEP_D ((W_FIRST_D - W_LAST_D) / (double)(B_N - 1))

// Sortable u32 keys: raw IEEE bits of difficulty (always > 0, so bit pattern
// is order-preserving). Ties (prob ~B^2*2^-32) cost ~1.7e-7 relative error,
// 4 orders of magnitude under the 1e-3 threshold -> strict '<' count is enough.
__device__ __align__(16) unsigned int g_keys[B_N];

#define K1_BLOCKS 1184   // 148 SMs * 8 blocks -> single persistent wave

// ---------------------------------------------------------------------------
// Kernel 1: difficulty[i] = 0.5*loss[i] + 0.5*||gradients[i,:]||_2
// Persistent: 1184 blocks x 256 threads, each block strides over rows.
// Streaming float4 loads, 4 independent accumulators.
// ---------------------------------------------------------------------------
__global__ __launch_bounds__(256) void difficulty_kernel(
    const float* __restrict__ loss,
    const float4* __restrict__ grad,       // [B, D/4]
    float* __restrict__ out)               // out[0]=acc, out[1..B]=difficulty
{
    const int tid = threadIdx.x;
    if (blockIdx.x == 0 && tid == 0) out[0] = 0.0f;   // reset accumulator

    __shared__ float warp_sums[8];

    for (int row = blockIdx.x; row < B_N; row += K1_BLOCKS) {
        const float4* __restrict__ g = grad + (size_t)row * (D_N / 4);

        float s0 = 0.0f, s1 = 0.0f, s2 = 0.0f, s3 = 0.0f;
#pragma unroll
        for (int it = 0; it < 4; it++) {
            float4 a = __ldcs(&g[tid + (it * 4 + 0) * 256]);
            float4 b = __ldcs(&g[tid + (it * 4 + 1) * 256]);
            float4 c = __ldcs(&g[tid + (it * 4 + 2) * 256]);
            float4 d = __ldcs(&g[tid + (it * 4 + 3) * 256]);
            s0 = fmaf(a.x, a.x, s0); s0 = fmaf(a.y, a.y, s0);
            s0 = fmaf(a.z, a.z, s0); s0 = fmaf(a.w, a.w, s0);
            s1 = fmaf(b.x, b.x, s1); s1 = fmaf(b.y, b.y, s1);
            s1 = fmaf(b.z, b.z, s1); s1 = fmaf(b.w, b.w, s1);
            s2 = fmaf(c.x, c.x, s2); s2 = fmaf(c.y, c.y, s2);
            s2 = fmaf(c.z, c.z, s2); s2 = fmaf(c.w, c.w, s2);
            s3 = fmaf(d.x, d.x, s3); s3 = fmaf(d.y, d.y, s3);
            s3 = fmaf(d.z, d.z, s3); s3 = fmaf(d.w, d.w, s3);
        }
        float s = (s0 + s1) + (s2 + s3);

        // warp reduce
#pragma unroll
        for (int off = 16; off > 0; off >>= 1)
            s += __shfl_xor_sync(0xFFFFFFFFu, s, off);

        if ((tid & 31) == 0) warp_sums[tid >> 5] = s;
        __syncthreads();

        if (tid == 0) {
            float tot = 0.0f;
#pragma unroll
            for (int w = 0; w < 8; w++) tot += warp_sums[w];
            float d = 0.5f * loss[row] + 0.5f * sqrtf(tot);
            out[1 + row] = d;
            g_keys[row] = __float_as_uint(d);
        }
        __syncthreads();   // protect warp_sums before next row
    }
}

// ---------------------------------------------------------------------------
// Kernel 2: counting rank + weighted loss accumulation (u32 keys).
// Each block owns 4 consecutive i's; 256 threads scan all B keys as uint4
// (4 u32 keys per 16B load) in a rolling loop (4 iters/thread); each load
// feeds 16 compares at ~2 SASS instr each.
// rank(i) = #{ key_j < key_i }
// One atomicAdd per block into out[0].
// ---------------------------------------------------------------------------
#define IPB 4          // i's per block
#define K2_THREADS 256

__global__ __launch_bounds__(K2_THREADS) void rank_weight_kernel(
    const float* __restrict__ loss,
    float* __restrict__ out)
{
    const int i0  = blockIdx.x * IPB;
    const int tid = threadIdx.x;

    unsigned int ki[IPB];
#pragma unroll
    for (int k = 0; k < IPB; k++) ki[k] = g_keys[i0 + k];

    int cnt[IPB] = {0, 0, 0, 0};

    const uint4* __restrict__ keys4 = (const uint4*)g_keys;  // 4 keys per uint4

#pragma unroll 4
    for (int p = tid; p < B_N / 4; p += K2_THREADS) {
        uint4 v = keys4[p];
#pragma unroll
        for (int k = 0; k < IPB; k++) {
            cnt[k] += (v.x < ki[k]);
            cnt[k] += (v.y < ki[k]);
            cnt[k] += (v.z < ki[k]);
            cnt[k] += (v.w < ki[k]);
        }
    }

    // warp reduce all 4 counters
#pragma unroll
    for (int off = 16; off > 0; off >>= 1) {
#pragma unroll
        for (int k = 0; k < IPB; k++)
            cnt[k] += __shfl_xor_sync(0xFFFFFFFFu, cnt[k], off);
    }

    __shared__ int warp_cnt[K2_THREADS / 32][IPB];
    if ((tid & 31) == 0) {
#pragma unroll
        for (int k = 0; k < IPB; k++)
            warp_cnt[tid >> 5][k] = cnt[k];
    }
    __syncthreads();

    if (tid == 0) {
        float contrib = 0.0f;
#pragma unroll
        for (int k = 0; k < IPB; k++) {
            int rank = 0;
#pragma unroll
            for (int w = 0; w < K2_THREADS / 32; w++) rank += warp_cnt[w][k];
            float wgt = (float)(W_FIRST_D - BATCH_STEP_D * (double)rank);
            contrib += __ldg(&loss[i0 + k]) * wgt;
        }
        atomicAdd(&out[0], contrib * (1.0f / (float)B_N));
    }
}

// ---------------------------------------------------------------------------
extern "C" void kernel_launch(void* const* d_in, const int* in_sizes, int n_in,
                              void* d_out, int out_size)
{
    const float*  loss = (const float*)d_in[0];
    const float4* grad = (const float4*)d_in[1];
    float* out = (float*)d_out;

    difficulty_kernel<<<K1_BLOCKS, 256>>>(loss, grad, out);
    rank_weight_kernel<<<B_N / IPB, K2_THREADS>>>(loss, out);
}

// round 10
// speedup vs baseline: 1.0285x; 1.0285x over previous
#include <cuda_runtime.h>
#include <math.h>
#include <stdint.h>

#define B_N 4096
#define D_N 16384

// W_FIRST = 2 - 10 * (2/49), W_LAST = 2 - W_FIRST, batch_step = (W_FIRST-W_LAST)/(B-1)
#define EPOCH_STEP (2.0 / 49.0)
#define W_FIRST_D  (2.0 - 10.0 * EPOCH_STEP)   /* ~1.5918367346938775 */
#define W_LAST_D   (2.0 - W_FIRST_D)
#define BATCH_STEP_D ((W_FIRST_D - W_LAST_D) / (double)(B_N - 1))

// Sortable u32 keys: raw IEEE bits of difficulty (always > 0, so bit pattern
// is order-preserving). Ties (prob ~B^2*2^-32) perturb the result ~1.7e-7
// relative, 4 orders under the 1e-3 threshold -> strict '<' count suffices.
__device__ __align__(16) unsigned int g_keys[B_N];

// ---------------------------------------------------------------------------
// Kernel 1 (R8-proven shape, 39.6us @ 6.8TB/s): one block per row, 256 thr,
// streaming float4 loads, 4 independent accumulators.
// Triggers the dependent K2 launch after its work is done (PDL).
// ---------------------------------------------------------------------------
__global__ __launch_bounds__(256) void difficulty_kernel(
    const float* __restrict__ loss,
    const float4* __restrict__ grad,       // [B, D/4]
    float* __restrict__ out)               // out[0]=acc, out[1..B]=difficulty
{
    const int row = blockIdx.x;
    const int tid = threadIdx.x;

    if (row == 0 && tid == 0) out[0] = 0.0f;   // reset accumulator (graph replay safe)

    const float4* __restrict__ g = grad + (size_t)row * (D_N / 4);

    float s0 = 0.0f, s1 = 0.0f, s2 = 0.0f, s3 = 0.0f;
#pragma unroll
    for (int it = 0; it < 4; it++) {
        float4 a = __ldcs(&g[tid + (it * 4 + 0) * 256]);
        float4 b = __ldcs(&g[tid + (it * 4 + 1) * 256]);
        float4 c = __ldcs(&g[tid + (it * 4 + 2) * 256]);
        float4 d = __ldcs(&g[tid + (it * 4 + 3) * 256]);
        s0 = fmaf(a.x, a.x, s0); s0 = fmaf(a.y, a.y, s0);
        s0 = fmaf(a.z, a.z, s0); s0 = fmaf(a.w, a.w, s0);
        s1 = fmaf(b.x, b.x, s1); s1 = fmaf(b.y, b.y, s1);
        s1 = fmaf(b.z, b.z, s1); s1 = fmaf(b.w, b.w, s1);
        s2 = fmaf(c.x, c.x, s2); s2 = fmaf(c.y, c.y, s2);
        s2 = fmaf(c.z, c.z, s2); s2 = fmaf(c.w, c.w, s2);
        s3 = fmaf(d.x, d.x, s3); s3 = fmaf(d.y, d.y, s3);
        s3 = fmaf(d.z, d.z, s3); s3 = fmaf(d.w, d.w, s3);
    }
    float s = (s0 + s1) + (s2 + s3);

    // warp reduce
#pragma unroll
    for (int off = 16; off > 0; off >>= 1)
        s += __shfl_xor_sync(0xFFFFFFFFu, s, off);

    __shared__ float warp_sums[8];
    if ((tid & 31) == 0) warp_sums[tid >> 5] = s;
    __syncthreads();

    if (tid == 0) {
        float tot = 0.0f;
#pragma unroll
        for (int w = 0; w < 8; w++) tot += warp_sums[w];
        float d = 0.5f * loss[row] + 0.5f * sqrtf(tot);
        out[1 + row] = d;
        g_keys[row] = __float_as_uint(d);
    }

    // PDL: allow the dependent rank kernel to launch; its griddepsync still
    // guarantees full memory visibility of g_keys/out before it reads them.
    cudaTriggerProgrammaticLaunchCompletion();
}

// ---------------------------------------------------------------------------
// Kernel 2: counting rank + weighted loss accumulation (u32 keys, PDL).
// Launched with ProgrammaticStreamSerialization: blocks spin up during K1's
// tail, wait at griddepsync, then run immediately when K1 completes.
// Each block owns 4 consecutive i's; 256 threads scan all B keys as uint4;
// REDUX warp reduction.
// ---------------------------------------------------------------------------
#define IPB 4          // i's per block
#define K2_THREADS 256

__global__ __launch_bounds__(K2_THREADS) void rank_weight_kernel(
    const float* __restrict__ loss,
    float* __restrict__ out)
{
    const int i0  = blockIdx.x * IPB;
    const int tid = threadIdx.x;

    // Prologue independent of K1's output, runs under K1's tail.
    float li = (tid == 0) ? __ldg(&loss[i0 + 0]) : 0.0f;
    float l1 = (tid == 0) ? __ldg(&loss[i0 + 1]) : 0.0f;
    float l2 = (tid == 0) ? __ldg(&loss[i0 + 2]) : 0.0f;
    float l3 = (tid == 0) ? __ldg(&loss[i0 + 3]) : 0.0f;

    // Wait for K1 grid completion (makes g_keys globally visible).
    cudaGridDependencySynchronize();

    unsigned int ki[IPB];
#pragma unroll
    for (int k = 0; k < IPB; k++) ki[k] = g_keys[i0 + k];

    int cnt[IPB] = {0, 0, 0, 0};

    const uint4* __restrict__ keys4 = (const uint4*)g_keys;  // 4 keys per uint4

#pragma unroll 4
    for (int p = tid; p < B_N / 4; p += K2_THREADS) {
        uint4 v = keys4[p];
#pragma unroll
        for (int k = 0; k < IPB; k++) {
            cnt[k] += (v.x < ki[k]);
            cnt[k] += (v.y < ki[k]);
            cnt[k] += (v.z < ki[k]);
            cnt[k] += (v.w < ki[k]);
        }
    }

    // REDUX warp reduction (single instruction per counter)
#pragma unroll
    for (int k = 0; k < IPB; k++)
        cnt[k] = __reduce_add_sync(0xFFFFFFFFu, cnt[k]);

    __shared__ int warp_cnt[K2_THREADS / 32][IPB];
    if ((tid & 31) == 0) {
#pragma unroll
        for (int k = 0; k < IPB; k++)
            warp_cnt[tid >> 5][k] = cnt[k];
    }
    __syncthreads();

    if (tid == 0) {
        int rank0 = 0, rank1 = 0, rank2 = 0, rank3 = 0;
#pragma unroll
        for (int w = 0; w < K2_THREADS / 32; w++) {
            rank0 += warp_cnt[w][0];
            rank1 += warp_cnt[w][1];
            rank2 += warp_cnt[w][2];
            rank3 += warp_cnt[w][3];
        }
        float contrib =
            li * (float)(W_FIRST_D - BATCH_STEP_D * (double)rank0) +
            l1 * (float)(W_FIRST_D - BATCH_STEP_D * (double)rank1) +
            l2 * (float)(W_FIRST_D - BATCH_STEP_D * (double)rank2) +
            l3 * (float)(W_FIRST_D - BATCH_STEP_D * (double)rank3);
        atomicAdd(&out[0], contrib * (1.0f / (float)B_N));
    }
}

// ---------------------------------------------------------------------------
extern "C" void kernel_launch(void* const* d_in, const int* in_sizes, int n_in,
                              void* d_out, int out_size)
{
    const float*  loss = (const float*)d_in[0];
    const float4* grad = (const float4*)d_in[1];
    float* out = (float*)d_out;

    difficulty_kernel<<<B_N, 256>>>(loss, grad, out);

    // PDL launch for K2: overlaps its ramp with K1's tail.
    cudaLaunchConfig_t cfg = {};
    cfg.gridDim  = dim3(B_N / IPB);
    cfg.blockDim = dim3(K2_THREADS);
    cfg.dynamicSmemBytes = 0;
    cfg.stream = 0;
    cudaLaunchAttribute attr[1];
    attr[0].id = cudaLaunchAttributeProgrammaticStreamSerialization;
    attr[0].val.programmaticStreamSerializationAllowed = 1;
    cfg.attrs = attr;
    cfg.numAttrs = 1;
    cudaLaunchKernelEx(&cfg, rank_weight_kernel, loss, out);
}